// round 16
// baseline (speedup 1.0000x reference)
#include <cuda_runtime.h>
#include <cstdint>

// ---------------------------------------------------------------------------
// MLPP on mma.sync m16n8k8 tf32 (sm_100 legacy tensor path; tcgen05 is not
// available under the harness's -arch=sm_100 compile target).
// Every op is a 256x256 GEMM over 131072 rows with gather pattern
//   addr(r,k) = rowBase(r) + (k>>4)*s1 + (k&15)*s0
// and identical scatter for the output. rowBase = 5-digit mixed-radix decode.
// R16 = R15 (proven: de-RMW G2-4, 4-array G5 fusion, R11 mainloop) + one
// isolated change: G2/G3/G4 merged into a single gridDim.z=3 launch (tgemm3,
// z-indexed weights/bias/output/descriptor). Removes 2 launch boundaries and
// lets the three x-gathers share L2.
// ---------------------------------------------------------------------------

#define N_ELEMS 33554432  // 4*32*32*32*256

__device__ float g_bufA[N_ELEMS];
__device__ float g_bufB[N_ELEMS];
__device__ float g_bufC[N_ELEMS];
__device__ float g_bufD[N_ELEMS];
__device__ float g_bufE[N_ELEMS];
__device__ float g_Wp[8][65536];   // fragment-permuted, tf32(RNA) weights

struct GDesc {
    int radix[5];    // slowest..fastest row digits
    int rstride[5];  // element strides per digit
    int s1, s0;      // k strides
};
struct P3 { GDesc d[3]; };
struct W3 { const float* w[3]; const float* b[3]; };
struct O3 { float* o[3]; };

__device__ __forceinline__ uint32_t f2tf32(float f) {
    uint32_t r; asm("cvt.rna.tf32.f32 %0, %1;" : "=r"(r) : "f"(f)); return r;
}
__device__ __forceinline__ uint32_t smem_u32(const void* p) {
    return (uint32_t)__cvta_generic_to_shared(p);
}
__device__ __forceinline__ void mma_tf32(float* c, const uint32_t* a,
                                         uint32_t b0, uint32_t b1) {
    asm volatile(
        "mma.sync.aligned.m16n8k8.row.col.f32.tf32.tf32.f32 "
        "{%0,%1,%2,%3}, {%4,%5,%6,%7}, {%8,%9}, {%0,%1,%2,%3};\n"
        : "+f"(c[0]), "+f"(c[1]), "+f"(c[2]), "+f"(c[3])
        : "r"(a[0]), "r"(a[1]), "r"(a[2]), "r"(a[3]), "r"(b0), "r"(b1));
}
__device__ __forceinline__ void ldsm_x4(uint32_t* r, uint32_t saddr) {
    asm volatile("ldmatrix.sync.aligned.m8n8.x4.shared.b16 {%0,%1,%2,%3}, [%4];"
        : "=r"(r[0]), "=r"(r[1]), "=r"(r[2]), "=r"(r[3]) : "r"(saddr));
}
__device__ __forceinline__ void cp16(uint32_t dst, const void* src) {
    asm volatile("cp.async.cg.shared.global [%0], [%1], 16;\n"
                 :: "r"(dst), "l"(src) : "memory");
}
__device__ __forceinline__ void cp4(uint32_t dst, const void* src) {
    asm volatile("cp.async.ca.shared.global [%0], [%1], 4;\n"
                 :: "r"(dst), "l"(src) : "memory");
}
__device__ __forceinline__ void cp_commit() {
    asm volatile("cp.async.commit_group;\n" ::: "memory");
}

// ---- Weight permute pre-kernel: Wp[(k>>4)*256 + n][perm(k&15)] = tf32(W[k][n])
__global__ void permW8(const float* w0, const float* w1, const float* w2, const float* w3,
                       const float* w4, const float* w5, const float* w6, const float* w7)
{
    const float* ws[8] = {w0, w1, w2, w3, w4, w5, w6, w7};
    int wi = blockIdx.y;
    int k  = blockIdx.x;          // 0..255
    int n  = threadIdx.x;         // 0..255
    float v = ws[wi][k * 256 + n];
    int kl = k & 15;
    int p  = ((kl & 3) << 2) | (kl >> 2);
    g_Wp[wi][(((k >> 4) * 256) + n) * 16 + p] = __uint_as_float(f2tf32(v));
}

// ---------------------------------------------------------------------------
// Shared GEMM body (BM=128 BN=128 BK=32, 8 warps 4Mx2N, 3-stage cp.async).
// Used by both the scalar-signature tgemm and the z-indexed tgemm3.
// ---------------------------------------------------------------------------
template<int AMODE, int EMODE, int GATHER>
__device__ __forceinline__ void gemm_body(
    const float* __restrict__ X, const float* __restrict__ X2,
    const float* __restrict__ X3, const float* __restrict__ X4,
    const float* __restrict__ Wp, const float* __restrict__ bias,
    const float* __restrict__ res, float* __restrict__ OUT, const GDesc& d)
{
    constexpr int ASTR  = 20;                 // A smem row stride (floats)
    constexpr int AFL   = 2 * 128 * ASTR;     // 5120 floats / stage
    constexpr int WFL   = 4096;               // 4096 floats / stage
    constexpr int STG_F = AFL + WFL;          // 9216 floats / stage
    constexpr int STG_B = STG_F * 4;          // bytes / stage
    extern __shared__ float sm[];
    __shared__ int rowAddr[128];

    const int tid = threadIdx.x;
    const int nb  = blockIdx.x;               // N-block: 0 / 1

    if (tid < 128) {
        int r = blockIdx.y * 128 + tid;
        int base = 0;
        #pragma unroll
        for (int i = 4; i >= 0; --i) {
            int dg = r % d.radix[i]; r /= d.radix[i];
            base += dg * d.rstride[i];
        }
        rowAddr[tid] = base;
    }
    __syncthreads();

    const int wid   = tid >> 5, lane = tid & 31;
    const int warpM = wid & 3,  warpN = wid >> 2;
    const int g     = lane >> 2, q    = lane & 3;
    const uint32_t smb = smem_u32(sm);

    // ---- per-thread running gather offsets (advance by 2*s1 per stage) ----
    int aoff4[4];  int ad4[4];    // GATHER==0 / AMODE==1
    int aoff16[16]; int ad16[16]; // GATHER==1
    if (GATHER == 0) {
        #pragma unroll
        for (int i = 0; i < 4; ++i) {
            int idx = tid + i * 256;              // 0..1023
            int row = idx >> 3, rem = idx & 7;
            int kg = rem >> 2, j = rem & 3;
            aoff4[i] = rowAddr[row] + kg * d.s1 + 4 * j;
            ad4[i]   = (kg * (128 * ASTR) + row * ASTR + 4 * j) * 4;
        }
    } else {
        #pragma unroll
        for (int i = 0; i < 16; ++i) {
            int idx = tid + i * 256;              // 0..4095
            int row = idx & 127, k = idx >> 7;    // rows contiguous in gmem
            aoff16[i] = rowAddr[row] + (k >> 4) * d.s1 + (k & 15) * d.s0;
            ad16[i]   = ((k >> 4) * (128 * ASTR) + row * ASTR + (k & 15)) * 4;
        }
    }
    // W: per-thread running offset (advance by 8192 floats per stage)
    int woff[4]; int wd4[4];
    #pragma unroll
    for (int i = 0; i < 4; ++i) {
        int idx4 = tid + i * 256;                 // 0..1023
        int kg = idx4 >> 9, off = idx4 & 511;
        woff[i] = (kg * 256 + nb * 128) * 16 + off * 4;
        wd4[i]  = (AFL + kg * 2048 + off * 4) * 4;
    }

    // ldmatrix per-thread fragment byte offsets (within a kg-block of A)
    const int m_ = lane >> 3, rt = lane & 7;
    int fo[2];
    #pragma unroll
    for (int mi = 0; mi < 2; ++mi)
        fo[mi] = ((warpM * 32 + mi * 16 + (m_ & 1) * 8 + rt) * ASTR + (m_ >> 1) * 4) * 4;

    float acc[2][8][4];
    #pragma unroll
    for (int mi = 0; mi < 2; ++mi)
        #pragma unroll
        for (int ni = 0; ni < 8; ++ni)
            #pragma unroll
            for (int j = 0; j < 4; ++j) acc[mi][ni][j] = 0.0f;

    auto issueA = [&](int p) {
        uint32_t ab = smb + p * STG_B;
        if (AMODE == 0) {
            if (GATHER == 0) {
                #pragma unroll
                for (int i = 0; i < 4; ++i) {
                    cp16(ab + ad4[i], X + aoff4[i]);
                    aoff4[i] += 2 * d.s1;
                }
            } else {
                #pragma unroll
                for (int i = 0; i < 16; ++i) {
                    cp4(ab + ad16[i], X + aoff16[i]);
                    aoff16[i] += 2 * d.s1;
                }
            }
        } else {
            float* abf = sm + p * STG_F;
            #pragma unroll
            for (int i = 0; i < 4; ++i) {
                int ga = aoff4[i];
                aoff4[i] += 2 * d.s1;
                float4 a1  = *reinterpret_cast<const float4*>(X  + ga);
                float4 s1v = *reinterpret_cast<const float4*>(X2 + ga);
                float4 s2v = *reinterpret_cast<const float4*>(X3 + ga);
                float4 s3v = *reinterpret_cast<const float4*>(X4 + ga);
                float4 v;
                v.x = (1.0f + a1.x) * (s1v.x + s2v.x + s3v.x);
                v.y = (1.0f + a1.y) * (s1v.y + s2v.y + s3v.y);
                v.z = (1.0f + a1.z) * (s1v.z + s2v.z + s3v.z);
                v.w = (1.0f + a1.w) * (s1v.w + s2v.w + s3v.w);
                *reinterpret_cast<float4*>(reinterpret_cast<char*>(abf) + ad4[i]) = v;
            }
        }
    };

    auto issueW = [&](int p) {
        uint32_t wbuf = smb + p * STG_B;
        #pragma unroll
        for (int i = 0; i < 4; ++i) {
            cp16(wbuf + wd4[i], Wp + woff[i]);
            woff[i] += 8192;                      // 2*256*16 floats per stage
        }
    };

    auto compute = [&](int p) {
        const uint32_t ab = smb + p * STG_B;
        const float* wbuf = sm + p * STG_F + AFL;
        #pragma unroll
        for (int kg = 0; kg < 2; ++kg) {
            uint32_t af[2][2][4];
            #pragma unroll
            for (int mi = 0; mi < 2; ++mi)
                #pragma unroll
                for (int kh = 0; kh < 2; ++kh)
                    ldsm_x4(af[mi][kh], ab + kg * (128 * ASTR * 4) + kh * 32 + fo[mi]);
            const float* W0 = wbuf + kg * 2048 + (warpN * 64) * 16 + 4 * q;
            #pragma unroll
            for (int ni = 0; ni < 8; ++ni) {
                float4 bv = *reinterpret_cast<const float4*>(W0 + (ni * 8 + g) * 16);
                uint32_t b0 = __float_as_uint(bv.x), b1 = __float_as_uint(bv.y);
                uint32_t b2 = __float_as_uint(bv.z), b3 = __float_as_uint(bv.w);
                #pragma unroll
                for (int mi = 0; mi < 2; ++mi) {
                    mma_tf32(acc[mi][ni], af[mi][0], b0, b1);
                    mma_tf32(acc[mi][ni], af[mi][1], b2, b3);
                }
            }
        }
    };

    // ---- 3-stage pipeline over 8 k32 stages ----
    issueA(0); issueW(0); cp_commit();
    issueA(1); issueW(1); cp_commit();

    #pragma unroll 1
    for (int s = 0; s < 8; ++s) {
        if (s < 7) asm volatile("cp.async.wait_group 1;\n" ::: "memory");
        else       asm volatile("cp.async.wait_group 0;\n" ::: "memory");
        __syncthreads();
        if (s < 6) { issueA((s + 2) % 3); issueW((s + 2) % 3); cp_commit(); }
        compute(s % 3);
    }

    // ---- epilogue: bias (+residual), scatter ----
    #pragma unroll
    for (int mi = 0; mi < 2; ++mi) {
        #pragma unroll
        for (int h = 0; h < 2; ++h) {
            int row  = warpM * 32 + mi * 16 + 8 * h + g;
            int base = rowAddr[row];
            #pragma unroll
            for (int ni = 0; ni < 8; ++ni) {
                int col = nb * 128 + warpN * 64 + ni * 8 + 2 * q;
                int a0  = base + (col >> 4) * d.s1 + (col & 15) * d.s0;
                int a1  = a0 + d.s0;
                float v0 = acc[mi][ni][2 * h + 0] + bias[col];
                float v1 = acc[mi][ni][2 * h + 1] + bias[col + 1];
                if (EMODE == 2) { v0 += res[a0]; v1 += res[a1]; }
                OUT[a0] = v0; OUT[a1] = v1;
            }
        }
    }
}

// Scalar-signature kernel (G1, G5, G6, G7, G8) — identical to R15.
template<int AMODE, int EMODE, int GATHER>
__global__ __launch_bounds__(256, 2)
void tgemm(const float* __restrict__ X, const float* __restrict__ X2,
           const float* __restrict__ X3, const float* __restrict__ X4,
           const float* __restrict__ Wp, const float* __restrict__ bias,
           const float* __restrict__ res, float* __restrict__ OUT, GDesc d)
{
    gemm_body<AMODE, EMODE, GATHER>(X, X2, X3, X4, Wp, bias, res, OUT, d);
}

// z-indexed kernel: 3 independent GEMMs (same template config) in one launch.
__global__ __launch_bounds__(256, 2)
void tgemm3(const float* __restrict__ X, W3 wb, O3 outs, P3 pd)
{
    const int z = blockIdx.z;
    gemm_body<0, 0, 0>(X, nullptr, nullptr, nullptr,
                       wb.w[z], wb.b[z], nullptr, outs.o[z], pd.d[z]);
}

// ---------------------------------------------------------------------------

extern "C" void kernel_launch(void* const* d_in, const int* in_sizes, int n_in,
                              void* d_out, int out_size)
{
    (void)in_sizes; (void)n_in; (void)out_size;

    const float* x      = (const float*)d_in[0];
    const float* W_h    = (const float*)d_in[1];
    const float* b_h    = (const float*)d_in[2];
    const float* W_w    = (const float*)d_in[3];
    const float* b_w    = (const float*)d_in[4];
    const float* W_c    = (const float*)d_in[5];
    const float* b_c    = (const float*)d_in[6];
    const float* W_d    = (const float*)d_in[7];
    const float* b_d    = (const float*)d_in[8];
    const float* W_attn = (const float*)d_in[9];
    const float* b_attn = (const float*)d_in[10];
    const float* W_1    = (const float*)d_in[11];
    const float* b_1    = (const float*)d_in[12];
    const float* W_2    = (const float*)d_in[13];
    const float* b_2    = (const float*)d_in[14];
    const float* W_3    = (const float*)d_in[15];
    const float* b_3    = (const float*)d_in[16];
    float* out = (float*)d_out;

    float *bufA, *bufB, *bufC, *bufD, *bufE, *wp;
    cudaGetSymbolAddress((void**)&bufA, g_bufA);
    cudaGetSymbolAddress((void**)&bufB, g_bufB);
    cudaGetSymbolAddress((void**)&bufC, g_bufC);
    cudaGetSymbolAddress((void**)&bufD, g_bufD);
    cudaGetSymbolAddress((void**)&bufE, g_bufE);
    cudaGetSymbolAddress((void**)&wp,   g_Wp);
    const float* Wp_h    = wp + 0 * 65536;
    const float* Wp_w    = wp + 1 * 65536;
    const float* Wp_c    = wp + 2 * 65536;
    const float* Wp_d    = wp + 3 * 65536;
    const float* Wp_attn = wp + 4 * 65536;
    const float* Wp_1    = wp + 5 * 65536;
    const float* Wp_2    = wp + 6 * 65536;
    const float* Wp_3    = wp + 7 * 65536;

    constexpr int SMEM = 3 * 9216 * 4;   // 110592 B (3 stages x 36 KB)
    cudaFuncSetAttribute(tgemm<0,0,1>, cudaFuncAttributeMaxDynamicSharedMemorySize, SMEM);
    cudaFuncSetAttribute(tgemm<0,0,0>, cudaFuncAttributeMaxDynamicSharedMemorySize, SMEM);
    cudaFuncSetAttribute(tgemm<1,2,0>, cudaFuncAttributeMaxDynamicSharedMemorySize, SMEM);
    cudaFuncSetAttribute(tgemm<0,2,0>, cudaFuncAttributeMaxDynamicSharedMemorySize, SMEM);
    cudaFuncSetAttribute(tgemm3,       cudaFuncAttributeMaxDynamicSharedMemorySize, SMEM);

    // x strides (elements): c=1, d=256, w=8192, h=262144, b=8388608
    GDesc d_att  = {{4, 2, 2, 32, 256}, {8388608, 4194304, 131072, 256, 1}, 262144, 8192};
    GDesc d_cont = {{1, 4, 32, 32, 32}, {0, 8388608, 262144, 8192, 256}, 16, 1};
    GDesc d_h    = {{4, 2, 32, 32, 16}, {8388608, 4194304, 8192, 256, 16}, 262144, 1};
    GDesc d_w    = {{4, 32, 2, 32, 16}, {8388608, 262144, 131072, 256, 16}, 8192, 1};
    GDesc d_d    = {{4, 32, 32, 2, 16}, {8388608, 262144, 8192, 4096, 16}, 256, 1};

    // permute + tf32(RNA)-round all 8 weight matrices (2 MB; trivial)
    permW8<<<dim3(256, 8), 256>>>(W_h, W_w, W_c, W_d, W_attn, W_1, W_2, W_3);

    dim3 grid(2, 1024), grid3(2, 1024, 3), block(256);

    P3 p_chw = {{d_cont, d_h, d_w}};
    W3 w_chw = {{Wp_c, Wp_h, Wp_w}, {b_c, b_h, b_w}};
    O3 o_chw = {{bufB, bufC, bufD}};   // tc, th, tw

    // Stage A (ip_mlp):
    // 1) t_att = attn(x)                              -> bufA
    tgemm<0,0,1><<<grid, block, SMEM>>>(x, nullptr, nullptr, nullptr,
                                        Wp_attn, b_attn, nullptr, bufA, d_att);
    // 2-4, ONE launch) tc = x@W_c ; th = xh@W_h ; tw = xw@W_w -> bufB/C/D
    tgemm3<<<grid3, block, SMEM>>>(x, w_chw, o_chw, p_chw);
    // 5) x1 = x + ((1+att)*(tc+th+tw)) @ W_1 + b_1    -> bufE
    tgemm<1,2,0><<<grid, block, SMEM>>>(bufA, bufB, bufC, bufD,
                                        Wp_1, b_1, x, bufE, d_cont);
    // Stage B (tp_mlp):
    // 6) t_d = dgather(x1) @ W_d + b_d                -> bufB  (tc dead)
    tgemm<0,0,0><<<grid, block, SMEM>>>(bufE, nullptr, nullptr, nullptr,
                                        Wp_d, b_d, nullptr, bufB, d_d);
    // 7) x2 = x1 + t_d @ W_2 + b_2                    -> bufC
    tgemm<0,2,0><<<grid, block, SMEM>>>(bufB, nullptr, nullptr, nullptr,
                                        Wp_2, b_2, bufE, bufC, d_cont);
    // Stage C:
    // 8) out = x2 + x2 @ W_3 + b_3                    -> d_out
    tgemm<0,2,0><<<grid, block, SMEM>>>(bufC, nullptr, nullptr, nullptr,
                                        Wp_3, b_3, bufC, out, d_cont);
}

// round 17
// speedup vs baseline: 1.0532x; 1.0532x over previous
#include <cuda_runtime.h>
#include <cstdint>

// ---------------------------------------------------------------------------
// MLPP on mma.sync m16n8k8 tf32 (sm_100 legacy tensor path; tcgen05 is not
// available under the harness's -arch=sm_100 compile target).
// Every op is a 256x256 GEMM over 131072 rows with gather pattern
//   addr(r,k) = rowBase(r) + (k>>4)*s1 + (k&15)*s0
// and identical scatter for the output. rowBase = 5-digit mixed-radix decode.
// R17 = R15 base (grid.z reverted — it regressed in R16) + G5 diet:
//   - G1 writes (1+att) via pre-biased 1+b_attn
//   - G4 epilogue sums: S = tw + tc[addr] + th[addr]  (EMODE=3, coalesced)
//   - G5 A-fusion is now a 2-stream product: a = (1+att)*S  (was 4-stream,
//     315us -> ~200us predicted)
// ---------------------------------------------------------------------------

#define N_ELEMS 33554432  // 4*32*32*32*256

__device__ float g_bufA[N_ELEMS];
__device__ float g_bufB[N_ELEMS];
__device__ float g_bufC[N_ELEMS];
__device__ float g_bufD[N_ELEMS];
__device__ float g_bufE[N_ELEMS];
__device__ float g_Wp[8][65536];   // fragment-permuted, tf32(RNA) weights
__device__ float g_biasP1[256];    // 1 + b_attn

struct GDesc {
    int radix[5];    // slowest..fastest row digits
    int rstride[5];  // element strides per digit
    int s1, s0;      // k strides
};

__device__ __forceinline__ uint32_t f2tf32(float f) {
    uint32_t r; asm("cvt.rna.tf32.f32 %0, %1;" : "=r"(r) : "f"(f)); return r;
}
__device__ __forceinline__ uint32_t smem_u32(const void* p) {
    return (uint32_t)__cvta_generic_to_shared(p);
}
__device__ __forceinline__ void mma_tf32(float* c, const uint32_t* a,
                                         uint32_t b0, uint32_t b1) {
    asm volatile(
        "mma.sync.aligned.m16n8k8.row.col.f32.tf32.tf32.f32 "
        "{%0,%1,%2,%3}, {%4,%5,%6,%7}, {%8,%9}, {%0,%1,%2,%3};\n"
        : "+f"(c[0]), "+f"(c[1]), "+f"(c[2]), "+f"(c[3])
        : "r"(a[0]), "r"(a[1]), "r"(a[2]), "r"(a[3]), "r"(b0), "r"(b1));
}
__device__ __forceinline__ void ldsm_x4(uint32_t* r, uint32_t saddr) {
    asm volatile("ldmatrix.sync.aligned.m8n8.x4.shared.b16 {%0,%1,%2,%3}, [%4];"
        : "=r"(r[0]), "=r"(r[1]), "=r"(r[2]), "=r"(r[3]) : "r"(saddr));
}
__device__ __forceinline__ void cp16(uint32_t dst, const void* src) {
    asm volatile("cp.async.cg.shared.global [%0], [%1], 16;\n"
                 :: "r"(dst), "l"(src) : "memory");
}
__device__ __forceinline__ void cp4(uint32_t dst, const void* src) {
    asm volatile("cp.async.ca.shared.global [%0], [%1], 4;\n"
                 :: "r"(dst), "l"(src) : "memory");
}
__device__ __forceinline__ void cp_commit() {
    asm volatile("cp.async.commit_group;\n" ::: "memory");
}

// ---- Weight permute pre-kernel: Wp[(k>>4)*256 + n][perm(k&15)] = tf32(W[k][n])
// Also fills g_biasP1 = 1 + b_attn (blockIdx.y==0, blockIdx.x==0 slice).
__global__ void permW8(const float* w0, const float* w1, const float* w2, const float* w3,
                       const float* w4, const float* w5, const float* w6, const float* w7,
                       const float* battn)
{
    const float* ws[8] = {w0, w1, w2, w3, w4, w5, w6, w7};
    int wi = blockIdx.y;
    int k  = blockIdx.x;          // 0..255
    int n  = threadIdx.x;         // 0..255
    if (wi == 0 && k == 0) g_biasP1[n] = 1.0f + battn[n];
    float v = ws[wi][k * 256 + n];
    int kl = k & 15;
    int p  = ((kl & 3) << 2) | (kl >> 2);
    g_Wp[wi][(((k >> 4) * 256) + n) * 16 + p] = __uint_as_float(f2tf32(v));
}

// ---------------------------------------------------------------------------
// BM=128 BN=128 BK=32, 8 warps (4Mx2N, warp tile 32x64), 3-stage cp.async.
// AMODE: 0: a = X[addr] (async) ; 1: a = X[addr]*X2[addr] (register-staged)
// EMODE: 0: OUT = acc+bias ; 2: OUT = res+acc+bias ;
//        3: OUT = acc+bias+X2[addr]+X3[addr]  (epilogue-sum, AMODE must be 0)
// GATHER: 0: s0==1 (cp.async 16B) ; 1: scalar gather / attn (cp.async 4B)
// ---------------------------------------------------------------------------
template<int AMODE, int EMODE, int GATHER>
__global__ __launch_bounds__(256, 2)
void tgemm(const float* __restrict__ X, const float* __restrict__ X2,
           const float* __restrict__ X3,
           const float* __restrict__ Wp, const float* __restrict__ bias,
           const float* __restrict__ res, float* __restrict__ OUT, GDesc d)
{
    constexpr int ASTR  = 20;                 // A smem row stride (floats)
    constexpr int AFL   = 2 * 128 * ASTR;     // 5120 floats / stage
    constexpr int WFL   = 4096;               // 4096 floats / stage
    constexpr int STG_F = AFL + WFL;          // 9216 floats / stage
    constexpr int STG_B = STG_F * 4;          // bytes / stage
    extern __shared__ float sm[];
    __shared__ int rowAddr[128];

    const int tid = threadIdx.x;
    const int nb  = blockIdx.x;               // N-block: 0 / 1

    if (tid < 128) {
        int r = blockIdx.y * 128 + tid;
        int base = 0;
        #pragma unroll
        for (int i = 4; i >= 0; --i) {
            int dg = r % d.radix[i]; r /= d.radix[i];
            base += dg * d.rstride[i];
        }
        rowAddr[tid] = base;
    }
    __syncthreads();

    const int wid   = tid >> 5, lane = tid & 31;
    const int warpM = wid & 3,  warpN = wid >> 2;
    const int g     = lane >> 2, q    = lane & 3;
    const uint32_t smb = smem_u32(sm);

    // ---- per-thread running gather offsets (advance by 2*s1 per stage) ----
    int aoff4[4];  int ad4[4];    // GATHER==0 / AMODE==1
    int aoff16[16]; int ad16[16]; // GATHER==1
    if (GATHER == 0) {
        #pragma unroll
        for (int i = 0; i < 4; ++i) {
            int idx = tid + i * 256;              // 0..1023
            int row = idx >> 3, rem = idx & 7;
            int kg = rem >> 2, j = rem & 3;
            aoff4[i] = rowAddr[row] + kg * d.s1 + 4 * j;
            ad4[i]   = (kg * (128 * ASTR) + row * ASTR + 4 * j) * 4;
        }
    } else {
        #pragma unroll
        for (int i = 0; i < 16; ++i) {
            int idx = tid + i * 256;              // 0..4095
            int row = idx & 127, k = idx >> 7;    // rows contiguous in gmem
            aoff16[i] = rowAddr[row] + (k >> 4) * d.s1 + (k & 15) * d.s0;
            ad16[i]   = ((k >> 4) * (128 * ASTR) + row * ASTR + (k & 15)) * 4;
        }
    }
    // W: per-thread running offset (advance by 8192 floats per stage)
    int woff[4]; int wd4[4];
    #pragma unroll
    for (int i = 0; i < 4; ++i) {
        int idx4 = tid + i * 256;                 // 0..1023
        int kg = idx4 >> 9, off = idx4 & 511;
        woff[i] = (kg * 256 + nb * 128) * 16 + off * 4;
        wd4[i]  = (AFL + kg * 2048 + off * 4) * 4;
    }

    // ldmatrix per-thread fragment byte offsets (within a kg-block of A)
    const int m_ = lane >> 3, rt = lane & 7;
    int fo[2];
    #pragma unroll
    for (int mi = 0; mi < 2; ++mi)
        fo[mi] = ((warpM * 32 + mi * 16 + (m_ & 1) * 8 + rt) * ASTR + (m_ >> 1) * 4) * 4;

    float acc[2][8][4];
    #pragma unroll
    for (int mi = 0; mi < 2; ++mi)
        #pragma unroll
        for (int ni = 0; ni < 8; ++ni)
            #pragma unroll
            for (int j = 0; j < 4; ++j) acc[mi][ni][j] = 0.0f;

    // ---- stage issue: A (async or register-staged) + W (async) ----
    auto issueA = [&](int p) {
        uint32_t ab = smb + p * STG_B;
        if (AMODE == 0) {
            if (GATHER == 0) {
                #pragma unroll
                for (int i = 0; i < 4; ++i) {
                    cp16(ab + ad4[i], X + aoff4[i]);
                    aoff4[i] += 2 * d.s1;
                }
            } else {
                #pragma unroll
                for (int i = 0; i < 16; ++i) {
                    cp4(ab + ad16[i], X + aoff16[i]);
                    aoff16[i] += 2 * d.s1;
                }
            }
        } else {
            float* abf = sm + p * STG_F;
            #pragma unroll
            for (int i = 0; i < 4; ++i) {
                int ga = aoff4[i];
                aoff4[i] += 2 * d.s1;
                float4 a1 = *reinterpret_cast<const float4*>(X  + ga);
                float4 sv = *reinterpret_cast<const float4*>(X2 + ga);
                float4 v;
                v.x = a1.x * sv.x;  v.y = a1.y * sv.y;
                v.z = a1.z * sv.z;  v.w = a1.w * sv.w;
                *reinterpret_cast<float4*>(reinterpret_cast<char*>(abf) + ad4[i]) = v;
            }
        }
    };

    auto issueW = [&](int p) {
        uint32_t wbuf = smb + p * STG_B;
        #pragma unroll
        for (int i = 0; i < 4; ++i) {
            cp16(wbuf + wd4[i], Wp + woff[i]);
            woff[i] += 8192;                      // 2*256*16 floats per stage
        }
    };

    auto compute = [&](int p) {
        const uint32_t ab = smb + p * STG_B;
        const float* wbuf = sm + p * STG_F + AFL;
        #pragma unroll
        for (int kg = 0; kg < 2; ++kg) {
            uint32_t af[2][2][4];
            #pragma unroll
            for (int mi = 0; mi < 2; ++mi)
                #pragma unroll
                for (int kh = 0; kh < 2; ++kh)
                    ldsm_x4(af[mi][kh], ab + kg * (128 * ASTR * 4) + kh * 32 + fo[mi]);
            const float* W0 = wbuf + kg * 2048 + (warpN * 64) * 16 + 4 * q;
            #pragma unroll
            for (int ni = 0; ni < 8; ++ni) {
                float4 bv = *reinterpret_cast<const float4*>(W0 + (ni * 8 + g) * 16);
                uint32_t b0 = __float_as_uint(bv.x), b1 = __float_as_uint(bv.y);
                uint32_t b2 = __float_as_uint(bv.z), b3 = __float_as_uint(bv.w);
                #pragma unroll
                for (int mi = 0; mi < 2; ++mi) {
                    mma_tf32(acc[mi][ni], af[mi][0], b0, b1);
                    mma_tf32(acc[mi][ni], af[mi][1], b2, b3);
                }
            }
        }
    };

    // ---- 3-stage pipeline over 8 k32 stages ----
    issueA(0); issueW(0); cp_commit();
    issueA(1); issueW(1); cp_commit();

    #pragma unroll 1
    for (int s = 0; s < 8; ++s) {
        if (s < 7) asm volatile("cp.async.wait_group 1;\n" ::: "memory");
        else       asm volatile("cp.async.wait_group 0;\n" ::: "memory");
        __syncthreads();
        if (s < 6) { issueA((s + 2) % 3); issueW((s + 2) % 3); cp_commit(); }
        compute(s % 3);
    }

    // ---- epilogue: bias (+residual / +epilogue-sum), scatter ----
    #pragma unroll
    for (int mi = 0; mi < 2; ++mi) {
        #pragma unroll
        for (int h = 0; h < 2; ++h) {
            int row  = warpM * 32 + mi * 16 + 8 * h + g;
            int base = rowAddr[row];
            #pragma unroll
            for (int ni = 0; ni < 8; ++ni) {
                int col = nb * 128 + warpN * 64 + ni * 8 + 2 * q;
                int a0  = base + (col >> 4) * d.s1 + (col & 15) * d.s0;
                int a1  = a0 + d.s0;
                float v0 = acc[mi][ni][2 * h + 0] + bias[col];
                float v1 = acc[mi][ni][2 * h + 1] + bias[col + 1];
                if (EMODE == 2) { v0 += res[a0]; v1 += res[a1]; }
                if (EMODE == 3) {
                    v0 += X2[a0] + X3[a0];
                    v1 += X2[a1] + X3[a1];
                }
                OUT[a0] = v0; OUT[a1] = v1;
            }
        }
    }
}

// ---------------------------------------------------------------------------

extern "C" void kernel_launch(void* const* d_in, const int* in_sizes, int n_in,
                              void* d_out, int out_size)
{
    (void)in_sizes; (void)n_in; (void)out_size;

    const float* x      = (const float*)d_in[0];
    const float* W_h    = (const float*)d_in[1];
    const float* b_h    = (const float*)d_in[2];
    const float* W_w    = (const float*)d_in[3];
    const float* b_w    = (const float*)d_in[4];
    const float* W_c    = (const float*)d_in[5];
    const float* b_c    = (const float*)d_in[6];
    const float* W_d    = (const float*)d_in[7];
    const float* b_d    = (const float*)d_in[8];
    const float* W_attn = (const float*)d_in[9];
    const float* b_attn = (const float*)d_in[10];
    const float* W_1    = (const float*)d_in[11];
    const float* b_1    = (const float*)d_in[12];
    const float* W_2    = (const float*)d_in[13];
    const float* b_2    = (const float*)d_in[14];
    const float* W_3    = (const float*)d_in[15];
    const float* b_3    = (const float*)d_in[16];
    float* out = (float*)d_out;

    float *bufA, *bufB, *bufC, *bufD, *bufE, *wp, *biasP1;
    cudaGetSymbolAddress((void**)&bufA, g_bufA);
    cudaGetSymbolAddress((void**)&bufB, g_bufB);
    cudaGetSymbolAddress((void**)&bufC, g_bufC);
    cudaGetSymbolAddress((void**)&bufD, g_bufD);
    cudaGetSymbolAddress((void**)&bufE, g_bufE);
    cudaGetSymbolAddress((void**)&wp,   g_Wp);
    cudaGetSymbolAddress((void**)&biasP1, g_biasP1);
    const float* Wp_h    = wp + 0 * 65536;
    const float* Wp_w    = wp + 1 * 65536;
    const float* Wp_c    = wp + 2 * 65536;
    const float* Wp_d    = wp + 3 * 65536;
    const float* Wp_attn = wp + 4 * 65536;
    const float* Wp_1    = wp + 5 * 65536;
    const float* Wp_2    = wp + 6 * 65536;
    const float* Wp_3    = wp + 7 * 65536;

    constexpr int SMEM = 3 * 9216 * 4;   // 110592 B (3 stages x 36 KB)
    cudaFuncSetAttribute(tgemm<0,0,1>, cudaFuncAttributeMaxDynamicSharedMemorySize, SMEM);
    cudaFuncSetAttribute(tgemm<0,0,0>, cudaFuncAttributeMaxDynamicSharedMemorySize, SMEM);
    cudaFuncSetAttribute(tgemm<0,3,0>, cudaFuncAttributeMaxDynamicSharedMemorySize, SMEM);
    cudaFuncSetAttribute(tgemm<1,2,0>, cudaFuncAttributeMaxDynamicSharedMemorySize, SMEM);
    cudaFuncSetAttribute(tgemm<0,2,0>, cudaFuncAttributeMaxDynamicSharedMemorySize, SMEM);

    // x strides (elements): c=1, d=256, w=8192, h=262144, b=8388608
    GDesc d_att  = {{4, 2, 2, 32, 256}, {8388608, 4194304, 131072, 256, 1}, 262144, 8192};
    GDesc d_cont = {{1, 4, 32, 32, 32}, {0, 8388608, 262144, 8192, 256}, 16, 1};
    GDesc d_h    = {{4, 2, 32, 32, 16}, {8388608, 4194304, 8192, 256, 16}, 262144, 1};
    GDesc d_w    = {{4, 32, 2, 32, 16}, {8388608, 262144, 131072, 256, 16}, 8192, 1};
    GDesc d_d    = {{4, 32, 32, 2, 16}, {8388608, 262144, 8192, 4096, 16}, 256, 1};

    // permute + tf32(RNA)-round all 8 weight matrices; also 1+b_attn
    permW8<<<dim3(256, 8), 256>>>(W_h, W_w, W_c, W_d, W_attn, W_1, W_2, W_3, b_attn);

    dim3 grid(2, 1024), block(256);

    // Stage A (ip_mlp):
    // 1) bufA = 1 + attn(x)            (pre-biased 1+b_attn)
    tgemm<0,0,1><<<grid, block, SMEM>>>(x, nullptr, nullptr,
                                        Wp_attn, biasP1, nullptr, bufA, d_att);
    // 2) tc = x @ W_c + b_c                           -> bufB
    tgemm<0,0,0><<<grid, block, SMEM>>>(x, nullptr, nullptr,
                                        Wp_c, b_c, nullptr, bufB, d_cont);
    // 3) th = xh(x) @ W_h + b_h                       -> bufC
    tgemm<0,0,0><<<grid, block, SMEM>>>(x, nullptr, nullptr,
                                        Wp_h, b_h, nullptr, bufC, d_h);
    // 4) S = xw(x)@W_w + b_w + tc + th                -> bufD  (epilogue sum)
    tgemm<0,3,0><<<grid, block, SMEM>>>(x, bufB, bufC,
                                        Wp_w, b_w, nullptr, bufD, d_w);
    // 5) x1 = x + ((1+att)*S) @ W_1 + b_1             -> bufE  (2-stream product)
    tgemm<1,2,0><<<grid, block, SMEM>>>(bufA, bufD, nullptr,
                                        Wp_1, b_1, x, bufE, d_cont);
    // Stage B (tp_mlp):
    // 6) t_d = dgather(x1) @ W_d + b_d                -> bufB  (tc dead)
    tgemm<0,0,0><<<grid, block, SMEM>>>(bufE, nullptr, nullptr,
                                        Wp_d, b_d, nullptr, bufB, d_d);
    // 7) x2 = x1 + t_d @ W_2 + b_2                    -> bufC
    tgemm<0,2,0><<<grid, block, SMEM>>>(bufB, nullptr, nullptr,
                                        Wp_2, b_2, bufE, bufC, d_cont);
    // Stage C:
    // 8) out = x2 + x2 @ W_3 + b_3                    -> d_out
    tgemm<0,2,0><<<grid, block, SMEM>>>(bufC, nullptr, nullptr,
                                        Wp_3, b_3, bufC, out, d_cont);
}